// round 1
// baseline (speedup 1.0000x reference)
#include <cuda_runtime.h>
#include <math.h>

// QSP expectation: Re(<0|U|0>) with U = S(phi0) * prod_k [W(theta) S(phi_k)].
// Key identity: the result is EXACTLY a degree-54 real polynomial in c = cos(theta)
// (even number of X-flips => only even powers of sin => s^2 = 1-c^2).
// Track p00 = A(c), p01 = s*B(c) with complex A,B:
//   A' = e_k * (c*A + i*(1-c^2)*B)
//   B' = conj(e_k) * (i*A + c*B)
// result f(c) = Re(e^{i phi0} * A(c)).
// Prologue: evaluate f at 55 Chebyshev nodes, DCT -> Chebyshev coefficients.
// Main: per element, Clenshaw evaluation (stable, coeffs O(1)).

#define QSP_DEPTH 27
#define NSTEPS (2 * QSP_DEPTH)   // 54
#define NCOEF  (NSTEPS + 1)      // 55

__device__ float g_coef[NCOEF];

__global__ void qsp_precompute(const float* __restrict__ p) {
    __shared__ float fsh[NCOEF];
    const float PI = 3.14159265358979323846f;
    int m = threadIdx.x;
    if (m < NCOEF) {
        float cm = cosf(PI * ((float)m + 0.5f) / (float)NCOEF);  // Chebyshev node
        float om = 1.0f - cm * cm;                               // (1 - c^2)
        float Ar = 1.f, Ai = 0.f, Br = 0.f, Bi = 0.f;
        #pragma unroll 1
        for (int k = 1; k <= NSTEPS; k++) {
            float ph = p[k];
            float er, ei;
            sincosf(ph, &ei, &er);
            // t1 = c*A + i*(1-c^2)*B
            float t1r = cm * Ar - om * Bi;
            float t1i = cm * Ai + om * Br;
            // t2 = i*A + c*B
            float t2r = cm * Br - Ai;
            float t2i = cm * Bi + Ar;
            // A' = e * t1 ; B' = conj(e) * t2
            Ar = er * t1r - ei * t1i;
            Ai = er * t1i + ei * t1r;
            Br = er * t2r + ei * t2i;
            Bi = er * t2i - ei * t2r;
        }
        float c0, s0;
        sincosf(p[0], &s0, &c0);
        fsh[m] = c0 * Ar - s0 * Ai;  // f(c_m) = Re(e^{i phi0} A)
    }
    __syncthreads();
    int k = threadIdx.x;
    if (k < NCOEF) {
        // DCT-II style Chebyshev coefficient extraction (exact for degree<=54 poly)
        float s = 0.f;
        #pragma unroll 1
        for (int m2 = 0; m2 < NCOEF; m2++)
            s += fsh[m2] * cosf(PI * (float)k * ((float)m2 + 0.5f) / (float)NCOEF);
        s *= 2.0f / (float)NCOEF;
        if (k == 0) s *= 0.5f;
        g_coef[k] = s;
    }
}

__global__ void __launch_bounds__(256) qsp_eval(
    const float4* __restrict__ x4,
    const float4* __restrict__ a4,
    const float*  __restrict__ bias,
    float4* __restrict__ out4,
    int n4)
{
    __shared__ float csh[NCOEF];
    if (threadIdx.x < NCOEF) csh[threadIdx.x] = g_coef[threadIdx.x];
    __syncthreads();

    int i = blockIdx.x * blockDim.x + threadIdx.x;
    if (i >= n4) return;

    float4 xv = x4[i];
    float4 av = a4[i];
    float  b0 = bias[0];

    float c[4], tc[4], b1[4], b2[4];
    c[0] = cosf(xv.x); c[1] = cosf(xv.y); c[2] = cosf(xv.z); c[3] = cosf(xv.w);
    #pragma unroll
    for (int j = 0; j < 4; j++) { tc[j] = 2.0f * c[j]; b1[j] = 0.f; b2[j] = 0.f; }

    // Clenshaw: b_k = 2c*b_{k+1} - b_{k+2} + a_k
    #pragma unroll
    for (int k = NSTEPS; k >= 1; k--) {
        float ak = csh[k];
        #pragma unroll
        for (int j = 0; j < 4; j++) {
            float bb = fmaf(tc[j], b1[j], ak - b2[j]);
            b2[j] = b1[j];
            b1[j] = bb;
        }
    }
    float a0 = csh[0];
    float f0 = fmaf(c[0], b1[0], a0 - b2[0]);
    float f1 = fmaf(c[1], b1[1], a0 - b2[1]);
    float f2 = fmaf(c[2], b1[2], a0 - b2[2]);
    float f3 = fmaf(c[3], b1[3], a0 - b2[3]);

    float4 o;
    o.x = fmaf(av.x, f0, b0);
    o.y = fmaf(av.y, f1, b0);
    o.z = fmaf(av.z, f2, b0);
    o.w = fmaf(av.w, f3, b0);
    out4[i] = o;
}

extern "C" void kernel_launch(void* const* d_in, const int* in_sizes, int n_in,
                              void* d_out, int out_size) {
    const float* x    = (const float*)d_in[0];
    const float* p    = (const float*)d_in[1];
    const float* al   = (const float*)d_in[2];
    const float* bias = (const float*)d_in[3];

    qsp_precompute<<<1, 64>>>(p);

    int n4 = out_size / 4;  // B = 524288 divisible by 4
    int threads = 256;
    int blocks = (n4 + threads - 1) / threads;
    qsp_eval<<<blocks, threads>>>((const float4*)x, (const float4*)al, bias,
                                  (float4*)d_out, n4);
}

// round 2
// speedup vs baseline: 2.1375x; 2.1375x over previous
#include <cuda_runtime.h>
#include <math.h>

// QSP expectation: Re(<0|U|0>), U = S(phi0) * prod_k [W(theta) S(phi_k)].
// f is EXACTLY a degree-54 real polynomial in c = cos(theta).
// Precompute (parallel): evaluate f at 55 Chebyshev nodes via SU(2) chunk
// products (9 chunks x 6 steps, 495 threads), DCT (exact integer angle
// reduction) -> Chebyshev coefficients stored as duplicated float2.
// Eval: Clenshaw with packed fp32x2 FMA (2 chains of 2 lanes per thread).

#define QSP_DEPTH 27
#define NSTEPS (2 * QSP_DEPTH)   // 54
#define NCOEF  (NSTEPS + 1)      // 55
#define NCHUNK 9
#define CSTEP  6                 // 9*6 = 54

__device__ float2 g_coef2[NCOEF];

typedef unsigned long long u64;

__device__ __forceinline__ u64 pack2(float lo, float hi) {
    u64 r; asm("mov.b64 %0, {%1, %2};" : "=l"(r) : "f"(lo), "f"(hi)); return r;
}
__device__ __forceinline__ void unpack2(u64 v, float& lo, float& hi) {
    asm("mov.b64 {%0, %1}, %2;" : "=f"(lo), "=f"(hi) : "l"(v));
}
__device__ __forceinline__ u64 fma2(u64 a, u64 b, u64 c) {
    u64 d; asm("fma.rn.f32x2 %0, %1, %2, %3;" : "=l"(d) : "l"(a), "l"(b), "l"(c)); return d;
}

// SU(2) compose helper: C = C * M, both as (a_r,a_i,b_r,b_i) meaning [[a,b],[-conj(b),conj(a)]]
#define SU2_COMPOSE(a_r,a_i,b_r,b_i, alr,ali,ber,bei) do {                   \
    float nar = a_r*alr - a_i*ali - b_r*ber - b_i*bei;                       \
    float nai = a_r*ali + a_i*alr + b_r*bei - b_i*ber;                       \
    float nbr = a_r*ber - a_i*bei + b_r*alr + b_i*ali;                       \
    float nbi = a_r*bei + a_i*ber + b_i*alr - b_r*ali;                       \
    a_r = nar; a_i = nai; b_r = nbr; b_i = nbi;                              \
} while (0)

__global__ void qsp_precompute(const float* __restrict__ p) {
    __shared__ float  ph[NCOEF];
    __shared__ float4 chunk[NCOEF * NCHUNK];   // 495 SU(2) partials
    __shared__ float  fsh[NCOEF];
    const float PI = 3.14159265358979323846f;
    int tid = threadIdx.x;

    if (tid < NCOEF) ph[tid] = p[tid];
    __syncthreads();

    // Phase 1: 495 threads, each computes product of 6 step-matrices at its node.
    if (tid < NCOEF * NCHUNK) {
        int m = tid / NCHUNK;
        int j = tid % NCHUNK;
        float th = PI * ((float)m + 0.5f) / (float)NCOEF;
        float cm, sm;
        sincosf(th, &sm, &cm);      // accurate node values
        float a_r = 1.f, a_i = 0.f, b_r = 0.f, b_i = 0.f;
        #pragma unroll
        for (int s = 0; s < CSTEP; s++) {
            int k = 1 + j * CSTEP + s;
            float er, ei;
            __sincosf(ph[k], &ei, &er);
            // M_k: alpha = c*e = cm*(er + i ei); beta = i*s*conj(e) = sm*ei + i*sm*er
            float alr = cm * er, ali = cm * ei;
            float ber = sm * ei, bei = sm * er;
            SU2_COMPOSE(a_r, a_i, b_r, b_i, alr, ali, ber, bei);
        }
        chunk[tid] = make_float4(a_r, a_i, b_r, b_i);
    }
    __syncthreads();

    // Phase 2: one thread per node composes its 9 chunk products (in order).
    if (tid < NCOEF) {
        float4 C = chunk[tid * NCHUNK];
        float a_r = C.x, a_i = C.y, b_r = C.z, b_i = C.w;
        #pragma unroll
        for (int j = 1; j < NCHUNK; j++) {
            float4 Mv = chunk[tid * NCHUNK + j];
            SU2_COMPOSE(a_r, a_i, b_r, b_i, Mv.x, Mv.y, Mv.z, Mv.w);
        }
        float c0, s0;
        sincosf(ph[0], &s0, &c0);
        fsh[tid] = c0 * a_r - s0 * a_i;   // f(c_m) = Re(e^{i phi0} * P00)
    }
    __syncthreads();

    // Phase 3: DCT -> Chebyshev coefficients. Angle pi*k*(m+0.5)/55 = pi*r/110,
    // r = k*(2m+1) reduced mod 220 EXACTLY in integers, then shifted to [-pi,pi)
    // so __cosf stays accurate: cos(pi*r/110) = -cos(pi*r/110 - pi).
    if (tid < NCOEF) {
        int k = tid;
        float s = 0.f;
        #pragma unroll 1
        for (int m = 0; m < NCOEF; m++) {
            int r = (k * (2 * m + 1)) % 220;
            float ang = (PI / 110.0f) * (float)r - PI;
            s = fmaf(fsh[m], -__cosf(ang), s);
        }
        s *= 2.0f / (float)NCOEF;
        if (k == 0) s *= 0.5f;
        g_coef2[k] = make_float2(s, s);   // duplicated for packed broadcast
    }
}

__global__ void __launch_bounds__(256) qsp_eval(
    const float4* __restrict__ x4,
    const float4* __restrict__ a4,
    const float*  __restrict__ bias,
    float4* __restrict__ out4,
    int n4)
{
    __shared__ float2 csh[NCOEF];
    if (threadIdx.x < NCOEF) csh[threadIdx.x] = g_coef2[threadIdx.x];
    __syncthreads();

    int i = blockIdx.x * blockDim.x + threadIdx.x;
    if (i >= n4) return;

    float4 xv = x4[i];
    float4 av = a4[i];
    float  b0 = __ldg(bias);

    float c0 = __cosf(xv.x), c1 = __cosf(xv.y), c2 = __cosf(xv.z), c3 = __cosf(xv.w);

    u64 tcA = pack2(2.0f * c0, 2.0f * c1);
    u64 tcB = pack2(2.0f * c2, 2.0f * c3);
    u64 neg1 = pack2(-1.0f, -1.0f);
    u64 b1A = 0ull, b2A = 0ull, b1B = 0ull, b2B = 0ull;

    // Clenshaw: b_k = 2c*b_{k+1} - b_{k+2} + a_k   (packed, 2 chains x 2 lanes)
    #pragma unroll
    for (int k = NSTEPS; k >= 1; k--) {
        float2 t = csh[k];                      // broadcast LDS.64
        u64 ak2; asm("mov.b64 %0, {%1, %2};" : "=l"(ak2) : "f"(t.x), "f"(t.y));
        u64 uA = fma2(neg1, b2A, ak2);          // ak - b2
        u64 uB = fma2(neg1, b2B, ak2);
        u64 nA = fma2(tcA, b1A, uA);
        u64 nB = fma2(tcB, b1B, uB);
        b2A = b1A; b1A = nA;
        b2B = b1B; b1B = nB;
    }

    float b1a0, b1a1, b1b0, b1b1, b2a0, b2a1, b2b0, b2b1;
    unpack2(b1A, b1a0, b1a1); unpack2(b2A, b2a0, b2a1);
    unpack2(b1B, b1b0, b1b1); unpack2(b2B, b2b0, b2b1);

    float a0 = csh[0].x;
    float f0 = fmaf(c0, b1a0, a0 - b2a0);
    float f1 = fmaf(c1, b1a1, a0 - b2a1);
    float f2 = fmaf(c2, b1b0, a0 - b2b0);
    float f3 = fmaf(c3, b1b1, a0 - b2b1);

    float4 o;
    o.x = fmaf(av.x, f0, b0);
    o.y = fmaf(av.y, f1, b0);
    o.z = fmaf(av.z, f2, b0);
    o.w = fmaf(av.w, f3, b0);
    out4[i] = o;
}

extern "C" void kernel_launch(void* const* d_in, const int* in_sizes, int n_in,
                              void* d_out, int out_size) {
    const float* x    = (const float*)d_in[0];
    const float* p    = (const float*)d_in[1];
    const float* al   = (const float*)d_in[2];
    const float* bias = (const float*)d_in[3];

    qsp_precompute<<<1, 512>>>(p);

    int n4 = out_size / 4;   // B = 524288, divisible by 4
    int threads = 256;
    int blocks = (n4 + threads - 1) / threads;
    qsp_eval<<<blocks, threads>>>((const float4*)x, (const float4*)al, bias,
                                  (float4*)d_out, n4);
}

// round 3
// speedup vs baseline: 3.1667x; 1.4815x over previous
#include <cuda_runtime.h>
#include <math.h>

// QSP expectation Re(<0|U|0>) = f(cos x), where f is a degree-54 polynomial
// with EVEN parity (54 degree-1 SU(2) factors, even # of off-diag picks).
// => f(c) = sum_{j=0}^{27} d_j T_{2j}(c) = sum_j d_j T_j(y),  y = 2c^2-1 = cos(2x).
// Single fused kernel: each block computes the 28 Chebyshev coefficients d_j
// redundantly in shared memory (28 nodes theta_m = pi(m+.5)/56, SU(2) chunk
// products, 28x28 DCT with exact integer angle reduction), then evaluates
// 8 elements/thread via a 27-step Clenshaw in y using packed fp32x2 FMA.

#define NSTEPS 54
#define NPH    55          // phases phi_0..phi_54
#define NNODE  28          // Chebyshev nodes in y (degree 27 exact)
#define NDEG   27
#define NCHUNK 9
#define CSTEP  6           // 9*6 = 54

typedef unsigned long long u64;

__device__ __forceinline__ u64 pack2(float lo, float hi) {
    u64 r; asm("mov.b64 %0, {%1, %2};" : "=l"(r) : "f"(lo), "f"(hi)); return r;
}
__device__ __forceinline__ void unpack2(u64 v, float& lo, float& hi) {
    asm("mov.b64 {%0, %1}, %2;" : "=f"(lo), "=f"(hi) : "l"(v));
}
__device__ __forceinline__ u64 fma2(u64 a, u64 b, u64 c) {
    u64 d; asm("fma.rn.f32x2 %0, %1, %2, %3;" : "=l"(d) : "l"(a), "l"(b), "l"(c)); return d;
}

// SU(2) compose: C = C * M, (a,b) meaning [[a,b],[-conj(b),conj(a)]]
#define SU2_COMPOSE(a_r,a_i,b_r,b_i, alr,ali,ber,bei) do {                   \
    float nar = a_r*alr - a_i*ali - b_r*ber - b_i*bei;                       \
    float nai = a_r*ali + a_i*alr + b_r*bei - b_i*ber;                       \
    float nbr = a_r*ber - a_i*bei + b_r*alr + b_i*ali;                       \
    float nbi = a_r*bei + a_i*ber + b_i*alr - b_r*ali;                       \
    a_r = nar; a_i = nai; b_r = nbr; b_i = nbi;                              \
} while (0)

__global__ void __launch_bounds__(256) qsp_fused(
    const float4* __restrict__ x4,
    const float*  __restrict__ p,
    const float4* __restrict__ a4,
    const float*  __restrict__ bias,
    float4* __restrict__ out4,
    int n4)
{
    __shared__ float  ph[NPH];
    __shared__ float4 chunk[NNODE * NCHUNK];   // 252 SU(2) partials
    __shared__ float  fsh[NNODE];
    __shared__ float2 csh[NNODE];              // duplicated coefficients
    const float PI = 3.14159265358979323846f;
    int tid = threadIdx.x;

    if (tid < NPH) ph[tid] = p[tid];
    __syncthreads();

    // Phase 1: 252 threads each compute a 6-step SU(2) partial product at node m.
    if (tid < NNODE * NCHUNK) {
        int m = tid / NCHUNK;
        int j = tid % NCHUNK;
        float th = PI * ((float)m + 0.5f) / 56.0f;   // theta_m: cos(2*theta_m)=y_m
        float cm, sm;
        sincosf(th, &sm, &cm);
        float a_r = 1.f, a_i = 0.f, b_r = 0.f, b_i = 0.f;
        #pragma unroll
        for (int s = 0; s < CSTEP; s++) {
            int k = 1 + j * CSTEP + s;
            float er, ei;
            __sincosf(ph[k], &ei, &er);
            float alr = cm * er, ali = cm * ei;   // alpha = c*e
            float ber = sm * ei, bei = sm * er;   // beta  = i*s*conj(e)
            SU2_COMPOSE(a_r, a_i, b_r, b_i, alr, ali, ber, bei);
        }
        chunk[tid] = make_float4(a_r, a_i, b_r, b_i);
    }
    __syncthreads();

    // Phase 2: one thread per node composes its 9 chunks (ordered).
    if (tid < NNODE) {
        float4 C = chunk[tid * NCHUNK];
        float a_r = C.x, a_i = C.y, b_r = C.z, b_i = C.w;
        #pragma unroll
        for (int j = 1; j < NCHUNK; j++) {
            float4 Mv = chunk[tid * NCHUNK + j];
            SU2_COMPOSE(a_r, a_i, b_r, b_i, Mv.x, Mv.y, Mv.z, Mv.w);
        }
        float c0, s0;
        sincosf(ph[0], &s0, &c0);
        fsh[tid] = c0 * a_r - s0 * a_i;   // f(theta_m) = Re(e^{i phi0} P00)
    }
    __syncthreads();

    // Phase 3: 28-point DCT -> d_j. Angle pi*j*(2m+1)/56 reduced mod 112 exactly.
    if (tid < NNODE) {
        int j = tid;
        float s = 0.f;
        #pragma unroll 1
        for (int m = 0; m < NNODE; m++) {
            int r = (j * (2 * m + 1)) % 112;
            float ang = (PI / 56.0f) * (float)r - PI;
            s = fmaf(fsh[m], -__cosf(ang), s);   // cos(pi r/56) = -cos(ang)
        }
        s *= 2.0f / (float)NNODE;
        if (j == 0) s *= 0.5f;
        csh[j] = make_float2(s, s);
    }
    __syncthreads();

    // Eval: 8 elements per thread, 4 packed Clenshaw chains in y = cos(2x).
    int i = blockIdx.x * blockDim.x + tid;          // 0..65535
    int stride = gridDim.x * blockDim.x;            // 65536; n4 = 131072
    int i2 = i + stride;
    if (i >= n4) return;

    float4 xv0 = x4[i];
    float4 xv1 = x4[i2];
    float4 av0 = a4[i];
    float4 av1 = a4[i2];
    float  b0  = __ldg(bias);

    float y0 = __cosf(2.0f * xv0.x), y1 = __cosf(2.0f * xv0.y);
    float y2 = __cosf(2.0f * xv0.z), y3 = __cosf(2.0f * xv0.w);
    float y4 = __cosf(2.0f * xv1.x), y5 = __cosf(2.0f * xv1.y);
    float y6 = __cosf(2.0f * xv1.z), y7 = __cosf(2.0f * xv1.w);

    u64 tyA = pack2(2.f*y0, 2.f*y1), tyB = pack2(2.f*y2, 2.f*y3);
    u64 tyC = pack2(2.f*y4, 2.f*y5), tyD = pack2(2.f*y6, 2.f*y7);
    u64 neg1 = pack2(-1.f, -1.f);
    u64 b1A=0, b2A=0, b1B=0, b2B=0, b1C=0, b2C=0, b1D=0, b2D=0;

    // Clenshaw: b_k = 2y*b_{k+1} - b_{k+2} + d_k
    #pragma unroll
    for (int k = NDEG; k >= 1; k--) {
        float2 t = csh[k];
        u64 dk2; asm("mov.b64 %0, {%1, %2};" : "=l"(dk2) : "f"(t.x), "f"(t.y));
        u64 uA = fma2(neg1, b2A, dk2);
        u64 uB = fma2(neg1, b2B, dk2);
        u64 uC = fma2(neg1, b2C, dk2);
        u64 uD = fma2(neg1, b2D, dk2);
        u64 nA = fma2(tyA, b1A, uA);
        u64 nB = fma2(tyB, b1B, uB);
        u64 nC = fma2(tyC, b1C, uC);
        u64 nD = fma2(tyD, b1D, uD);
        b2A=b1A; b1A=nA;  b2B=b1B; b1B=nB;
        b2C=b1C; b1C=nC;  b2D=b1D; b1D=nD;
    }

    float d0 = csh[0].x;
    float p1a,p1b,p2a,p2b;

    float4 o0, o1;
    unpack2(b1A,p1a,p1b); unpack2(b2A,p2a,p2b);
    o0.x = fmaf(av0.x, fmaf(y0, p1a, d0 - p2a), b0);
    o0.y = fmaf(av0.y, fmaf(y1, p1b, d0 - p2b), b0);
    unpack2(b1B,p1a,p1b); unpack2(b2B,p2a,p2b);
    o0.z = fmaf(av0.z, fmaf(y2, p1a, d0 - p2a), b0);
    o0.w = fmaf(av0.w, fmaf(y3, p1b, d0 - p2b), b0);
    unpack2(b1C,p1a,p1b); unpack2(b2C,p2a,p2b);
    o1.x = fmaf(av1.x, fmaf(y4, p1a, d0 - p2a), b0);
    o1.y = fmaf(av1.y, fmaf(y5, p1b, d0 - p2b), b0);
    unpack2(b1D,p1a,p1b); unpack2(b2D,p2a,p2b);
    o1.z = fmaf(av1.z, fmaf(y6, p1a, d0 - p2a), b0);
    o1.w = fmaf(av1.w, fmaf(y7, p1b, d0 - p2b), b0);

    out4[i]  = o0;
    out4[i2] = o1;
}

extern "C" void kernel_launch(void* const* d_in, const int* in_sizes, int n_in,
                              void* d_out, int out_size) {
    const float* x    = (const float*)d_in[0];
    const float* p    = (const float*)d_in[1];
    const float* al   = (const float*)d_in[2];
    const float* bias = (const float*)d_in[3];

    int n4 = out_size / 4;           // 131072
    int threads = 256;
    int blocks = (n4 / 2 + threads - 1) / threads;   // 256 blocks, 8 elem/thread
    qsp_fused<<<blocks, threads>>>((const float4*)x, p, (const float4*)al, bias,
                                   (float4*)d_out, n4);
}